// round 1
// baseline (speedup 1.0000x reference)
#include <cuda_runtime.h>

// ---------------------------------------------------------------------------
// GNN VAE: x_recon, z, pred = f(x, edge_index, weights)
// Strategy: build CSR (by dst) once per launch, then gather-style propagation
// (no float atomics), fused small MLPs, smem-tiled fp32 GEMMs.
// ---------------------------------------------------------------------------

#define MAXN 50048
#define MAXE 800256

__device__ int   g_cnt[MAXN];
__device__ int   g_cursor[MAXN];
__device__ int   g_rowptr[MAXN + 1];
__device__ float g_dinv[MAXN];
__device__ int2  g_csr[MAXE];                 // {src, weight-as-bits}
__device__ float g_h1[(size_t)MAXN * 64];     // x @ W_enc_gnn
__device__ float g_h1r[(size_t)MAXN * 64];    // relu(gcn1)
__device__ float g_hd[(size_t)MAXN * 64];     // relu(z @ W_dec_fc + b)
__device__ float g_h2[(size_t)MAXN * 256];    // hd @ W_dec_gnn

// ---------------------------------------------------------------- init / deg
__global__ void k_init(int n) {
    int i = blockIdx.x * blockDim.x + threadIdx.x;
    if (i < n) { g_cnt[i] = 0; g_cursor[i] = 0; }
}

__global__ void k_count(const int* __restrict__ dst, int E) {
    int i = blockIdx.x * blockDim.x + threadIdx.x;
    if (i < E) atomicAdd(&g_cnt[dst[i]], 1);
}

__global__ void k_dinv(int n) {
    int i = blockIdx.x * blockDim.x + threadIdx.x;
    if (i < n) g_dinv[i] = rsqrtf((float)(g_cnt[i] + 1));  // +1 self loop
}

// single-block exclusive scan of g_cnt -> g_rowptr
__global__ void k_scan(int n) {
    __shared__ int sh[1024];
    __shared__ int carry;
    int t = threadIdx.x;
    if (t == 0) { carry = 0; g_rowptr[0] = 0; }
    __syncthreads();
    for (int base = 0; base < n; base += 1024) {
        int i = base + t;
        int v = (i < n) ? g_cnt[i] : 0;
        sh[t] = v;
        __syncthreads();
        for (int off = 1; off < 1024; off <<= 1) {
            int tmp = (t >= off) ? sh[t - off] : 0;
            __syncthreads();
            sh[t] += tmp;
            __syncthreads();
        }
        if (i < n) g_rowptr[i + 1] = carry + sh[t];
        __syncthreads();
        if (t == 0) carry += sh[1023];
        __syncthreads();
    }
}

__global__ void k_fill(const int* __restrict__ src, const int* __restrict__ dst, int E) {
    int i = blockIdx.x * blockDim.x + threadIdx.x;
    if (i >= E) return;
    int s = src[i], d = dst[i];
    int pos = atomicAdd(&g_cursor[d], 1);
    float w = g_dinv[s] * g_dinv[d];
    g_csr[g_rowptr[d] + pos] = make_int2(s, __float_as_int(w));
}

// ---------------------------------------------------- GEMM1: [N,256]@[256,64]
// thread-per-row, 64 register accumulators, W in 64KB smem (broadcast LDS)
__global__ void k_gemm1(const float* __restrict__ x, const float* __restrict__ W, int n) {
    extern __shared__ float Wsm[];  // 256*64 floats
    for (int i = threadIdx.x; i < 256 * 64 / 4; i += blockDim.x)
        ((float4*)Wsm)[i] = ((const float4*)W)[i];
    __syncthreads();

    int row = blockIdx.x * blockDim.x + threadIdx.x;
    if (row >= n) return;

    float4 acc[16];
#pragma unroll
    for (int j = 0; j < 16; j++) acc[j] = make_float4(0.f, 0.f, 0.f, 0.f);

    const float4* xr = (const float4*)(x + (size_t)row * 256);
    for (int k4 = 0; k4 < 64; k4++) {
        float4 xv = __ldg(xr + k4);
        const float4* wrow = ((const float4*)Wsm) + k4 * 4 * 16;
#pragma unroll
        for (int kk = 0; kk < 4; kk++) {
            float xk = (kk == 0) ? xv.x : (kk == 1) ? xv.y : (kk == 2) ? xv.z : xv.w;
#pragma unroll
            for (int j = 0; j < 16; j++) {
                float4 w = wrow[kk * 16 + j];
                acc[j].x += xk * w.x;
                acc[j].y += xk * w.y;
                acc[j].z += xk * w.z;
                acc[j].w += xk * w.w;
            }
        }
    }
    float4* o = (float4*)(g_h1 + (size_t)row * 64);
#pragma unroll
    for (int j = 0; j < 16; j++) o[j] = acc[j];
}

// -------------------------------------------- prop1: gather, dim=64, + relu
__global__ void k_prop1(const float* __restrict__ b, int n) {
    int gw = (blockIdx.x * blockDim.x + threadIdx.x) >> 5;
    int lane = threadIdx.x & 31;
    if (gw >= n) return;
    float di = g_dinv[gw];
    float dii = di * di;
    const float2* hrow = (const float2*)(g_h1 + (size_t)gw * 64);
    float2 acc = hrow[lane];
    acc.x *= dii; acc.y *= dii;
    int beg = g_rowptr[gw], end = g_rowptr[gw + 1];
    for (int e = beg; e < end; e++) {
        int2 ed = g_csr[e];
        float w = __int_as_float(ed.y);
        float2 v = ((const float2*)(g_h1 + (size_t)ed.x * 64))[lane];
        acc.x += v.x * w;
        acc.y += v.y * w;
    }
    float2 bb = ((const float2*)b)[lane];
    acc.x = fmaxf(acc.x + bb.x, 0.f);
    acc.y = fmaxf(acc.y + bb.y, 0.f);
    ((float2*)(g_h1r + (size_t)gw * 64))[lane] = acc;
}

// ------------------- fused MLPs: z = h@Wef+bef; hd = relu(z@Wdf+bdf); pred
__global__ void k_mlp(const float* __restrict__ Wef, const float* __restrict__ bef,
                      const float* __restrict__ Wdf, const float* __restrict__ bdf,
                      const float* __restrict__ Wc,  const float* __restrict__ bc,
                      float* __restrict__ out_z, float* __restrict__ out_pr, int n) {
    __shared__ float o_s[8][64];
    __shared__ float z_s[8][32];
    int wl = threadIdx.x >> 5, lane = threadIdx.x & 31;
    int row = (blockIdx.x * blockDim.x + threadIdx.x) >> 5;
    if (row >= n) return;
    o_s[wl][lane]      = g_h1r[(size_t)row * 64 + lane];
    o_s[wl][lane + 32] = g_h1r[(size_t)row * 64 + lane + 32];
    __syncwarp();
    // z (32 wide, one per lane)
    float s = bef[lane];
#pragma unroll
    for (int k = 0; k < 64; k++) s += o_s[wl][k] * Wef[k * 32 + lane];
    z_s[wl][lane] = s;
    out_z[(size_t)row * 32 + lane] = s;
    __syncwarp();
    // hd (64 wide, 2 per lane)
    float c0 = bdf[lane], c1 = bdf[lane + 32];
#pragma unroll
    for (int k = 0; k < 32; k++) {
        float zk = z_s[wl][k];
        c0 += zk * Wdf[k * 64 + lane];
        c1 += zk * Wdf[k * 64 + lane + 32];
    }
    g_hd[(size_t)row * 64 + lane]      = fmaxf(c0, 0.f);
    g_hd[(size_t)row * 64 + lane + 32] = fmaxf(c1, 0.f);
    // pred (3 wide)
    if (lane < 3) {
        float p = bc[lane];
#pragma unroll
        for (int k = 0; k < 32; k++) p += z_s[wl][k] * Wc[k * 3 + lane];
        out_pr[(size_t)row * 3 + lane] = p;
    }
}

// ---------------------------------------------- GEMM2: [N,64]@[64,256]
// warp-per-row, hd broadcast via shfl, W in 64KB smem
__global__ void k_gemm2(const float* __restrict__ W, int n) {
    extern __shared__ float Wsm[];  // 64*256 floats
    for (int i = threadIdx.x; i < 64 * 256 / 4; i += blockDim.x)
        ((float4*)Wsm)[i] = ((const float4*)W)[i];
    __syncthreads();

    int gw = (blockIdx.x * blockDim.x + threadIdx.x) >> 5;
    int lane = threadIdx.x & 31;
    if (gw >= n) return;

    float2 hv = ((const float2*)(g_hd + (size_t)gw * 64))[lane];  // k = 2*lane, 2*lane+1
    float4 a0 = make_float4(0.f, 0.f, 0.f, 0.f);
    float4 a1 = make_float4(0.f, 0.f, 0.f, 0.f);
    const float4* Wsm4 = (const float4*)Wsm;  // row stride: 64 float4
#pragma unroll
    for (int k = 0; k < 64; k++) {
        float hk = __shfl_sync(0xFFFFFFFFu, (k & 1) ? hv.y : hv.x, k >> 1);
        float4 w0 = Wsm4[k * 64 + lane];
        float4 w1 = Wsm4[k * 64 + 32 + lane];
        a0.x += hk * w0.x; a0.y += hk * w0.y; a0.z += hk * w0.z; a0.w += hk * w0.w;
        a1.x += hk * w1.x; a1.y += hk * w1.y; a1.z += hk * w1.z; a1.w += hk * w1.w;
    }
    float4* o = (float4*)(g_h2 + (size_t)gw * 256);
    o[lane] = a0;
    o[lane + 32] = a1;
}

// -------------------------------------------- prop2: gather, dim=256
__global__ void k_prop2(const float* __restrict__ b, float* __restrict__ outx, int n) {
    int gw = (blockIdx.x * blockDim.x + threadIdx.x) >> 5;
    int lane = threadIdx.x & 31;
    if (gw >= n) return;
    float di = g_dinv[gw];
    float dii = di * di;
    const float4* hrow = (const float4*)(g_h2 + (size_t)gw * 256);
    float4 a0 = hrow[lane], a1 = hrow[lane + 32];
    a0.x *= dii; a0.y *= dii; a0.z *= dii; a0.w *= dii;
    a1.x *= dii; a1.y *= dii; a1.z *= dii; a1.w *= dii;
    int beg = g_rowptr[gw], end = g_rowptr[gw + 1];
    for (int e = beg; e < end; e++) {
        int2 ed = g_csr[e];
        float w = __int_as_float(ed.y);
        const float4* vr = (const float4*)(g_h2 + (size_t)ed.x * 256);
        float4 v0 = vr[lane], v1 = vr[lane + 32];
        a0.x += v0.x * w; a0.y += v0.y * w; a0.z += v0.z * w; a0.w += v0.w * w;
        a1.x += v1.x * w; a1.y += v1.y * w; a1.z += v1.z * w; a1.w += v1.w * w;
    }
    const float4* b4 = (const float4*)b;
    float4 b0 = b4[lane], b1 = b4[lane + 32];
    a0.x += b0.x; a0.y += b0.y; a0.z += b0.z; a0.w += b0.w;
    a1.x += b1.x; a1.y += b1.y; a1.z += b1.z; a1.w += b1.w;
    float4* o = (float4*)(outx + (size_t)gw * 256);
    o[lane] = a0;
    o[lane + 32] = a1;
}

// ---------------------------------------------------------------------------
extern "C" void kernel_launch(void* const* d_in, const int* in_sizes, int n_in,
                              void* d_out, int out_size) {
    const float* x     = (const float*)d_in[0];
    const int*   ei    = (const int*)d_in[1];
    // d_in[2] = edge_attr (unused by reference)
    const float* W_enc = (const float*)d_in[3];
    const float* b_enc = (const float*)d_in[4];
    const float* W_ef  = (const float*)d_in[5];
    const float* b_ef  = (const float*)d_in[6];
    const float* W_df  = (const float*)d_in[7];
    const float* b_df  = (const float*)d_in[8];
    const float* W_dec = (const float*)d_in[9];
    const float* b_dec = (const float*)d_in[10];
    const float* W_c   = (const float*)d_in[11];
    const float* b_c   = (const float*)d_in[12];

    int N = in_sizes[0] / 256;
    int E = in_sizes[1] / 2;
    const int* src = ei;
    const int* dst = ei + E;

    float* out    = (float*)d_out;
    float* out_xr = out;
    float* out_z  = out + (size_t)N * 256;
    float* out_pr = out_z + (size_t)N * 32;

    cudaFuncSetAttribute(k_gemm1, cudaFuncAttributeMaxDynamicSharedMemorySize, 65536);
    cudaFuncSetAttribute(k_gemm2, cudaFuncAttributeMaxDynamicSharedMemorySize, 65536);

    int gbN  = (N + 255) / 256;
    int gbE  = (E + 255) / 256;
    int gbW  = (N + 7) / 8;  // warp-per-node, 8 warps/block

    k_init <<<gbN, 256>>>(N);
    k_count<<<gbE, 256>>>(dst, E);
    k_dinv <<<gbN, 256>>>(N);
    k_scan <<<1, 1024>>>(N);
    k_fill <<<gbE, 256>>>(src, dst, E);
    k_gemm1<<<gbN, 256, 65536>>>(x, W_enc, N);
    k_prop1<<<gbW, 256>>>(b_enc, N);
    k_mlp  <<<gbW, 256>>>(W_ef, b_ef, W_df, b_df, W_c, b_c, out_z, out_pr, N);
    k_gemm2<<<gbW, 256, 65536>>>(W_dec, N);
    k_prop2<<<gbW, 256>>>(b_dec, out_xr, N);
}

// round 2
// speedup vs baseline: 1.1990x; 1.1990x over previous
#include <cuda_runtime.h>

// ---------------------------------------------------------------------------
// GNN VAE on GB300. CSR-by-dst build (hierarchical scan), gather propagation
// (no float atomics), packed f32x2 FFMA GEMMs, fused MLPs.
// ---------------------------------------------------------------------------

#define MAXN 50048
#define MAXE 800256

typedef unsigned long long u64;

__device__ __forceinline__ u64 pack2(float x, float y) {
    u64 r; asm("mov.b64 %0, {%1,%2};" : "=l"(r) : "f"(x), "f"(y)); return r;
}
__device__ __forceinline__ void ffma2(u64 &d, u64 a, u64 b) {
    asm("fma.rn.f32x2 %0, %1, %2, %0;" : "+l"(d) : "l"(a), "l"(b));
}
__device__ __forceinline__ u64 add2(u64 a, u64 b) {
    u64 r; asm("add.rn.f32x2 %0, %1, %2;" : "=l"(r) : "l"(a), "l"(b)); return r;
}

__device__ int   g_cnt[MAXN];
__device__ int   g_cursor[MAXN];
__device__ int   g_rowptr[MAXN + 1];
__device__ int   g_bsum[128];
__device__ int   g_boff[128];
__device__ float g_dinv[MAXN];
__device__ __align__(16) int2  g_csr[MAXE];               // {src, weight bits}
__device__ __align__(256) float g_h1[(size_t)MAXN * 64];  // x @ W_enc_gnn
__device__ __align__(256) float g_h1r[(size_t)MAXN * 64]; // relu(gcn1)
__device__ __align__(256) float g_hd[(size_t)MAXN * 64];  // relu(z @ W_dec_fc + b)
__device__ __align__(256) float g_h2[(size_t)MAXN * 256]; // hd @ W_dec_gnn

// ---------------------------------------------------------------- init / deg
__global__ void k_init(int n) {
    int i = blockIdx.x * blockDim.x + threadIdx.x;
    if (i < n) g_cnt[i] = 0;
}

__global__ void k_count(const int* __restrict__ dst, int E) {
    int i = blockIdx.x * blockDim.x + threadIdx.x;
    if (i < E) atomicAdd(&g_cnt[dst[i]], 1);
}

// ----------------------------------------------------- hierarchical scan
// A: per-block (1024 elems) inclusive scan -> rowptr (local), block totals
__global__ void k_scan_a(int n) {
    __shared__ int wsum[32];
    int t = threadIdx.x;
    int gid = blockIdx.x * 1024 + t;
    int lane = t & 31, w = t >> 5;
    int v = (gid < n) ? g_cnt[gid] : 0;
    int s = v;
#pragma unroll
    for (int o = 1; o < 32; o <<= 1) {
        int u = __shfl_up_sync(0xFFFFFFFFu, s, o);
        if (lane >= o) s += u;
    }
    if (lane == 31) wsum[w] = s;
    __syncthreads();
    if (w == 0) {
        int ws = wsum[lane];
#pragma unroll
        for (int o = 1; o < 32; o <<= 1) {
            int u = __shfl_up_sync(0xFFFFFFFFu, ws, o);
            if (lane >= o) ws += u;
        }
        wsum[lane] = ws;
    }
    __syncthreads();
    int incl = s + (w > 0 ? wsum[w - 1] : 0);
    if (gid < n) g_rowptr[gid + 1] = incl;
    if (t == 1023) g_bsum[blockIdx.x] = incl;
}

// B: scan the (<=128) block totals -> exclusive offsets
__global__ void k_scan_b(int nblk) {
    __shared__ int sh[128];
    int t = threadIdx.x;
    sh[t] = (t < nblk) ? g_bsum[t] : 0;
    __syncthreads();
#pragma unroll
    for (int o = 1; o < 128; o <<= 1) {
        int u = (t >= o) ? sh[t - o] : 0;
        __syncthreads();
        sh[t] += u;
        __syncthreads();
    }
    g_boff[t] = (t > 0) ? sh[t - 1] : 0;
    if (t == 0) g_rowptr[0] = 0;
}

// C: add block offsets; also compute dinv and zero cursors (fused)
__global__ void k_scan_c(int n) {
    int i = blockIdx.x * blockDim.x + threadIdx.x;
    if (i >= n) return;
    g_rowptr[i + 1] += g_boff[i >> 10];
    g_dinv[i] = rsqrtf((float)(g_cnt[i] + 1));  // +1 self loop
    g_cursor[i] = 0;
}

__global__ void k_fill(const int* __restrict__ src, const int* __restrict__ dst, int E) {
    int i = blockIdx.x * blockDim.x + threadIdx.x;
    if (i >= E) return;
    int s = src[i], d = dst[i];
    int pos = atomicAdd(&g_cursor[d], 1);
    float w = g_dinv[s] * g_dinv[d];
    g_csr[g_rowptr[d] + pos] = make_int2(s, __float_as_int(w));
}

// ---------------------------------------------------- GEMM1: [N,256]@[256,64]
// thread-per-row, 32 f32x2 accumulators, W in 64KB smem (broadcast LDS)
__global__ void k_gemm1(const float* __restrict__ x, const float* __restrict__ W, int n) {
    extern __shared__ float Wsm[];  // 256*64 floats
    for (int i = threadIdx.x; i < 256 * 64 / 4; i += blockDim.x)
        ((float4*)Wsm)[i] = ((const float4*)W)[i];
    __syncthreads();

    int row = blockIdx.x * blockDim.x + threadIdx.x;
    if (row >= n) return;

    u64 acc[32];
#pragma unroll
    for (int j = 0; j < 32; j++) acc[j] = 0ull;

    const float4* xr = (const float4*)(x + (size_t)row * 256);
    for (int k4 = 0; k4 < 64; k4++) {
        float4 xv = __ldg(xr + k4);
#pragma unroll
        for (int kk = 0; kk < 4; kk++) {
            float xk = (kk == 0) ? xv.x : (kk == 1) ? xv.y : (kk == 2) ? xv.z : xv.w;
            u64 xx = pack2(xk, xk);
            const ulonglong2* wrow = (const ulonglong2*)(Wsm + (k4 * 4 + kk) * 64);
#pragma unroll
            for (int j = 0; j < 16; j++) {
                ulonglong2 w = wrow[j];
                ffma2(acc[2 * j],     xx, w.x);
                ffma2(acc[2 * j + 1], xx, w.y);
            }
        }
    }
    ulonglong2* o = (ulonglong2*)(g_h1 + (size_t)row * 64);
#pragma unroll
    for (int j = 0; j < 16; j++) { ulonglong2 t; t.x = acc[2 * j]; t.y = acc[2 * j + 1]; o[j] = t; }
}

// -------------------------------------------- prop1: gather, dim=64, + relu
__global__ void k_prop1(const float* __restrict__ b, int n) {
    int gw = (blockIdx.x * blockDim.x + threadIdx.x) >> 5;
    int lane = threadIdx.x & 31;
    if (gw >= n) return;
    float di = g_dinv[gw];
    u64 dii = pack2(di * di, di * di);
    u64 self = ((const u64*)(g_h1 + (size_t)gw * 64))[lane];
    u64 acc = 0ull;
    ffma2(acc, self, dii);
    int e = g_rowptr[gw], end = g_rowptr[gw + 1];
    for (; e + 2 <= end; e += 2) {
        int2 e0 = g_csr[e], e1 = g_csr[e + 1];
        float w0 = __int_as_float(e0.y), w1 = __int_as_float(e1.y);
        u64 v0 = ((const u64*)(g_h1 + (size_t)e0.x * 64))[lane];
        u64 v1 = ((const u64*)(g_h1 + (size_t)e1.x * 64))[lane];
        ffma2(acc, v0, pack2(w0, w0));
        ffma2(acc, v1, pack2(w1, w1));
    }
    if (e < end) {
        int2 e0 = g_csr[e];
        float w0 = __int_as_float(e0.y);
        u64 v0 = ((const u64*)(g_h1 + (size_t)e0.x * 64))[lane];
        ffma2(acc, v0, pack2(w0, w0));
    }
    u64 bb = ((const u64*)b)[lane];
    float2 r = *(float2*)&acc;
    float2 bf = *(float2*)&bb;
    r.x = fmaxf(r.x + bf.x, 0.f);
    r.y = fmaxf(r.y + bf.y, 0.f);
    ((float2*)(g_h1r + (size_t)gw * 64))[lane] = r;
}

// ------------------- fused MLPs: z = h@Wef+bef; hd = relu(z@Wdf+bdf); pred
__global__ void k_mlp(const float* __restrict__ Wef, const float* __restrict__ bef,
                      const float* __restrict__ Wdf, const float* __restrict__ bdf,
                      const float* __restrict__ Wc,  const float* __restrict__ bc,
                      float* __restrict__ out_z, float* __restrict__ out_pr, int n) {
    __shared__ float o_s[8][64];
    __shared__ float z_s[8][32];
    int wl = threadIdx.x >> 5, lane = threadIdx.x & 31;
    int row = (blockIdx.x * blockDim.x + threadIdx.x) >> 5;
    if (row >= n) return;
    o_s[wl][lane]      = g_h1r[(size_t)row * 64 + lane];
    o_s[wl][lane + 32] = g_h1r[(size_t)row * 64 + lane + 32];
    __syncwarp();
    float s = bef[lane];
#pragma unroll
    for (int k = 0; k < 64; k++) s += o_s[wl][k] * Wef[k * 32 + lane];
    z_s[wl][lane] = s;
    out_z[(size_t)row * 32 + lane] = s;
    __syncwarp();
    float c0 = bdf[lane], c1 = bdf[lane + 32];
#pragma unroll
    for (int k = 0; k < 32; k++) {
        float zk = z_s[wl][k];
        c0 += zk * Wdf[k * 64 + lane];
        c1 += zk * Wdf[k * 64 + lane + 32];
    }
    g_hd[(size_t)row * 64 + lane]      = fmaxf(c0, 0.f);
    g_hd[(size_t)row * 64 + lane + 32] = fmaxf(c1, 0.f);
    if (lane < 3) {
        float p = bc[lane];
#pragma unroll
        for (int k = 0; k < 32; k++) p += z_s[wl][k] * Wc[k * 3 + lane];
        out_pr[(size_t)row * 3 + lane] = p;
    }
}

// ---------------------------------------------- GEMM2: [N,64]@[64,256]
// warp-per-row, hd broadcast via shfl, W in 64KB smem, f32x2 FMAs
__global__ void k_gemm2(const float* __restrict__ W, int n) {
    extern __shared__ float Wsm[];  // 64*256 floats
    for (int i = threadIdx.x; i < 64 * 256 / 4; i += blockDim.x)
        ((float4*)Wsm)[i] = ((const float4*)W)[i];
    __syncthreads();

    int gw = (blockIdx.x * blockDim.x + threadIdx.x) >> 5;
    int lane = threadIdx.x & 31;
    if (gw >= n) return;

    float2 hv = ((const float2*)(g_hd + (size_t)gw * 64))[lane];  // k = 2*lane, 2*lane+1
    u64 acc[4] = {0ull, 0ull, 0ull, 0ull};
    const ulonglong2* W2 = (const ulonglong2*)Wsm;  // 64 ulonglong2 per row
#pragma unroll
    for (int k = 0; k < 64; k++) {
        float hk = __shfl_sync(0xFFFFFFFFu, (k & 1) ? hv.y : hv.x, k >> 1);
        u64 hh = pack2(hk, hk);
        ulonglong2 w0 = W2[k * 64 + lane];
        ulonglong2 w1 = W2[k * 64 + 32 + lane];
        ffma2(acc[0], hh, w0.x);
        ffma2(acc[1], hh, w0.y);
        ffma2(acc[2], hh, w1.x);
        ffma2(acc[3], hh, w1.y);
    }
    ulonglong2* o = (ulonglong2*)(g_h2 + (size_t)gw * 256);
    ulonglong2 t0; t0.x = acc[0]; t0.y = acc[1];
    ulonglong2 t1; t1.x = acc[2]; t1.y = acc[3];
    o[lane] = t0;
    o[lane + 32] = t1;
}

// -------------------------------------------- prop2: gather, dim=256
__global__ void k_prop2(const float* __restrict__ b, float* __restrict__ outx, int n) {
    int gw = (blockIdx.x * blockDim.x + threadIdx.x) >> 5;
    int lane = threadIdx.x & 31;
    if (gw >= n) return;
    float di = g_dinv[gw];
    u64 dii = pack2(di * di, di * di);
    const ulonglong2* hrow = (const ulonglong2*)(g_h2 + (size_t)gw * 256);
    ulonglong2 h0 = hrow[lane], h1 = hrow[lane + 32];
    u64 acc[4] = {0ull, 0ull, 0ull, 0ull};
    ffma2(acc[0], h0.x, dii);
    ffma2(acc[1], h0.y, dii);
    ffma2(acc[2], h1.x, dii);
    ffma2(acc[3], h1.y, dii);
    int e = g_rowptr[gw], end = g_rowptr[gw + 1];
    for (; e + 2 <= end; e += 2) {
        int2 e0 = g_csr[e], e1 = g_csr[e + 1];
        u64 w0 = pack2(__int_as_float(e0.y), __int_as_float(e0.y));
        u64 w1 = pack2(__int_as_float(e1.y), __int_as_float(e1.y));
        const ulonglong2* r0 = (const ulonglong2*)(g_h2 + (size_t)e0.x * 256);
        const ulonglong2* r1 = (const ulonglong2*)(g_h2 + (size_t)e1.x * 256);
        ulonglong2 a0 = r0[lane], a1 = r0[lane + 32];
        ulonglong2 c0 = r1[lane], c1 = r1[lane + 32];
        ffma2(acc[0], a0.x, w0); ffma2(acc[1], a0.y, w0);
        ffma2(acc[2], a1.x, w0); ffma2(acc[3], a1.y, w0);
        ffma2(acc[0], c0.x, w1); ffma2(acc[1], c0.y, w1);
        ffma2(acc[2], c1.x, w1); ffma2(acc[3], c1.y, w1);
    }
    if (e < end) {
        int2 e0 = g_csr[e];
        u64 w0 = pack2(__int_as_float(e0.y), __int_as_float(e0.y));
        const ulonglong2* r0 = (const ulonglong2*)(g_h2 + (size_t)e0.x * 256);
        ulonglong2 a0 = r0[lane], a1 = r0[lane + 32];
        ffma2(acc[0], a0.x, w0); ffma2(acc[1], a0.y, w0);
        ffma2(acc[2], a1.x, w0); ffma2(acc[3], a1.y, w0);
    }
    const ulonglong2* b2 = (const ulonglong2*)b;
    ulonglong2 b0 = b2[lane], b1 = b2[lane + 32];
    ulonglong2 t0, t1;
    t0.x = add2(acc[0], b0.x); t0.y = add2(acc[1], b0.y);
    t1.x = add2(acc[2], b1.x); t1.y = add2(acc[3], b1.y);
    ulonglong2* o = (ulonglong2*)(outx + (size_t)gw * 256);
    o[lane] = t0;
    o[lane + 32] = t1;
}

// ---------------------------------------------------------------------------
extern "C" void kernel_launch(void* const* d_in, const int* in_sizes, int n_in,
                              void* d_out, int out_size) {
    const float* x     = (const float*)d_in[0];
    const int*   ei    = (const int*)d_in[1];
    // d_in[2] = edge_attr (unused by reference)
    const float* W_enc = (const float*)d_in[3];
    const float* b_enc = (const float*)d_in[4];
    const float* W_ef  = (const float*)d_in[5];
    const float* b_ef  = (const float*)d_in[6];
    const float* W_df  = (const float*)d_in[7];
    const float* b_df  = (const float*)d_in[8];
    const float* W_dec = (const float*)d_in[9];
    const float* b_dec = (const float*)d_in[10];
    const float* W_c   = (const float*)d_in[11];
    const float* b_c   = (const float*)d_in[12];

    int N = in_sizes[0] / 256;
    int E = in_sizes[1] / 2;
    const int* src = ei;
    const int* dst = ei + E;

    float* out    = (float*)d_out;
    float* out_xr = out;
    float* out_z  = out + (size_t)N * 256;
    float* out_pr = out_z + (size_t)N * 32;

    cudaFuncSetAttribute(k_gemm1, cudaFuncAttributeMaxDynamicSharedMemorySize, 65536);
    cudaFuncSetAttribute(k_gemm2, cudaFuncAttributeMaxDynamicSharedMemorySize, 65536);

    int gbN   = (N + 255) / 256;
    int gbE   = (E + 255) / 256;
    int gbW   = (N + 7) / 8;          // warp-per-node, 8 warps/block
    int nblk  = (N + 1023) / 1024;    // scan blocks

    k_init  <<<gbN, 256>>>(N);
    k_count <<<gbE, 256>>>(dst, E);
    k_scan_a<<<nblk, 1024>>>(N);
    k_scan_b<<<1, 128>>>(nblk);
    k_scan_c<<<gbN, 256>>>(N);
    k_fill  <<<gbE, 256>>>(src, dst, E);
    k_gemm1 <<<gbN, 256, 65536>>>(x, W_enc, N);
    k_prop1 <<<gbW, 256>>>(b_enc, N);
    k_mlp   <<<gbW, 256>>>(W_ef, b_ef, W_df, b_df, W_c, b_c, out_z, out_pr, N);
    k_gemm2 <<<gbW, 256, 65536>>>(W_dec, N);
    k_prop2 <<<gbW, 256>>>(b_dec, out_xr, N);
}

// round 3
// speedup vs baseline: 1.3399x; 1.1175x over previous
#include <cuda_runtime.h>

// ---------------------------------------------------------------------------
// GNN VAE on GB300. CSR-by-dst build (hierarchical scan), gather propagation
// (no float atomics). KEY: decoder GCN uses propagate-THEN-transform
// (A_norm (hd W) == (A_norm hd) W), cutting edge-gather traffic 4x.
// ---------------------------------------------------------------------------

#define MAXN 50048
#define MAXE 800256

typedef unsigned long long u64;

__device__ __forceinline__ u64 pack2(float x, float y) {
    u64 r; asm("mov.b64 %0, {%1,%2};" : "=l"(r) : "f"(x), "f"(y)); return r;
}
__device__ __forceinline__ void ffma2(u64 &d, u64 a, u64 b) {
    asm("fma.rn.f32x2 %0, %1, %2, %0;" : "+l"(d) : "l"(a), "l"(b));
}
__device__ __forceinline__ u64 add2(u64 a, u64 b) {
    u64 r; asm("add.rn.f32x2 %0, %1, %2;" : "=l"(r) : "l"(a), "l"(b)); return r;
}

__device__ int   g_cnt[MAXN];
__device__ int   g_cursor[MAXN];
__device__ int   g_rowptr[MAXN + 1];
__device__ int   g_bsum[128];
__device__ int   g_boff[128];
__device__ float g_dinv[MAXN];
__device__ __align__(16) int2  g_csr[MAXE];               // {src, weight bits}
__device__ __align__(256) float g_h1[(size_t)MAXN * 64];  // x @ W_enc_gnn
__device__ __align__(256) float g_hd[(size_t)MAXN * 64];  // relu(z @ W_dec_fc + b)
__device__ __align__(256) float g_pd[(size_t)MAXN * 64];  // A_norm @ hd

// ---------------------------------------------------------------- init / deg
__global__ void k_init(int n) {
    int i = blockIdx.x * blockDim.x + threadIdx.x;
    if (i < n) g_cnt[i] = 0;
}

__global__ void k_count(const int* __restrict__ dst, int E) {
    int i = blockIdx.x * blockDim.x + threadIdx.x;
    if (i < E) atomicAdd(&g_cnt[dst[i]], 1);
}

// ----------------------------------------------------- hierarchical scan
__global__ void k_scan_a(int n) {
    __shared__ int wsum[32];
    int t = threadIdx.x;
    int gid = blockIdx.x * 1024 + t;
    int lane = t & 31, w = t >> 5;
    int v = (gid < n) ? g_cnt[gid] : 0;
    int s = v;
#pragma unroll
    for (int o = 1; o < 32; o <<= 1) {
        int u = __shfl_up_sync(0xFFFFFFFFu, s, o);
        if (lane >= o) s += u;
    }
    if (lane == 31) wsum[w] = s;
    __syncthreads();
    if (w == 0) {
        int ws = wsum[lane];
#pragma unroll
        for (int o = 1; o < 32; o <<= 1) {
            int u = __shfl_up_sync(0xFFFFFFFFu, ws, o);
            if (lane >= o) ws += u;
        }
        wsum[lane] = ws;
    }
    __syncthreads();
    int incl = s + (w > 0 ? wsum[w - 1] : 0);
    if (gid < n) g_rowptr[gid + 1] = incl;
    if (t == 1023) g_bsum[blockIdx.x] = incl;
}

__global__ void k_scan_b(int nblk) {
    __shared__ int sh[128];
    int t = threadIdx.x;
    sh[t] = (t < nblk) ? g_bsum[t] : 0;
    __syncthreads();
#pragma unroll
    for (int o = 1; o < 128; o <<= 1) {
        int u = (t >= o) ? sh[t - o] : 0;
        __syncthreads();
        sh[t] += u;
        __syncthreads();
    }
    g_boff[t] = (t > 0) ? sh[t - 1] : 0;
    if (t == 0) g_rowptr[0] = 0;
}

__global__ void k_scan_c(int n) {
    int i = blockIdx.x * blockDim.x + threadIdx.x;
    if (i >= n) return;
    g_rowptr[i + 1] += g_boff[i >> 10];
    g_dinv[i] = rsqrtf((float)(g_cnt[i] + 1));  // +1 self loop
    g_cursor[i] = 0;
}

__global__ void k_fill(const int* __restrict__ src, const int* __restrict__ dst, int E) {
    int i = blockIdx.x * blockDim.x + threadIdx.x;
    if (i >= E) return;
    int s = src[i], d = dst[i];
    int pos = atomicAdd(&g_cursor[d], 1);
    float w = g_dinv[s] * g_dinv[d];
    g_csr[g_rowptr[d] + pos] = make_int2(s, __float_as_int(w));
}

// ---------------------------------------------------- GEMM1: [N,256]@[256,64]
__global__ void k_gemm1(const float* __restrict__ x, const float* __restrict__ W, int n) {
    extern __shared__ float Wsm[];  // 256*64 floats
    for (int i = threadIdx.x; i < 256 * 64 / 4; i += blockDim.x)
        ((float4*)Wsm)[i] = ((const float4*)W)[i];
    __syncthreads();

    int row = blockIdx.x * blockDim.x + threadIdx.x;
    if (row >= n) return;

    u64 acc[32];
#pragma unroll
    for (int j = 0; j < 32; j++) acc[j] = 0ull;

    const float4* xr = (const float4*)(x + (size_t)row * 256);
    for (int k4 = 0; k4 < 64; k4++) {
        float4 xv = __ldg(xr + k4);
#pragma unroll
        for (int kk = 0; kk < 4; kk++) {
            float xk = (kk == 0) ? xv.x : (kk == 1) ? xv.y : (kk == 2) ? xv.z : xv.w;
            u64 xx = pack2(xk, xk);
            const ulonglong2* wrow = (const ulonglong2*)(Wsm + (k4 * 4 + kk) * 64);
#pragma unroll
            for (int j = 0; j < 16; j++) {
                ulonglong2 w = wrow[j];
                ffma2(acc[2 * j],     xx, w.x);
                ffma2(acc[2 * j + 1], xx, w.y);
            }
        }
    }
    ulonglong2* o = (ulonglong2*)(g_h1 + (size_t)row * 64);
#pragma unroll
    for (int j = 0; j < 16; j++) { ulonglong2 t; t.x = acc[2 * j]; t.y = acc[2 * j + 1]; o[j] = t; }
}

// ------------- fused: prop1 (gather, 64-d, +bias +relu) THEN encoder MLPs
// z = h@Wef+bef (-> out_z); hd = relu(z@Wdf+bdf) (-> g_hd); pred (-> out_pr)
__global__ void k_prop1_mlp(const float* __restrict__ b,
                            const float* __restrict__ Wef, const float* __restrict__ bef,
                            const float* __restrict__ Wdf, const float* __restrict__ bdf,
                            const float* __restrict__ Wc,  const float* __restrict__ bc,
                            float* __restrict__ out_z, float* __restrict__ out_pr, int n) {
    __shared__ float o_s[8][64];
    __shared__ float z_s[8][32];
    int wl = threadIdx.x >> 5, lane = threadIdx.x & 31;
    int gw = (blockIdx.x * blockDim.x + threadIdx.x) >> 5;
    if (gw >= n) return;

    // ---- propagation over dim 64 (float2 per lane)
    float di = g_dinv[gw];
    u64 dii = pack2(di * di, di * di);
    u64 self = ((const u64*)(g_h1 + (size_t)gw * 64))[lane];
    u64 acc = 0ull;
    ffma2(acc, self, dii);
    int e = g_rowptr[gw], end = g_rowptr[gw + 1];
    for (; e + 2 <= end; e += 2) {
        int2 e0 = g_csr[e], e1 = g_csr[e + 1];
        u64 v0 = ((const u64*)(g_h1 + (size_t)e0.x * 64))[lane];
        u64 v1 = ((const u64*)(g_h1 + (size_t)e1.x * 64))[lane];
        ffma2(acc, v0, pack2(__int_as_float(e0.y), __int_as_float(e0.y)));
        ffma2(acc, v1, pack2(__int_as_float(e1.y), __int_as_float(e1.y)));
    }
    if (e < end) {
        int2 e0 = g_csr[e];
        u64 v0 = ((const u64*)(g_h1 + (size_t)e0.x * 64))[lane];
        ffma2(acc, v0, pack2(__int_as_float(e0.y), __int_as_float(e0.y)));
    }
    float2 r = *(float2*)&acc;
    float2 bf = ((const float2*)b)[lane];
    r.x = fmaxf(r.x + bf.x, 0.f);
    r.y = fmaxf(r.y + bf.y, 0.f);
    o_s[wl][2 * lane]     = r.x;
    o_s[wl][2 * lane + 1] = r.y;
    __syncwarp();

    // ---- z (32 wide)
    float s = bef[lane];
#pragma unroll
    for (int k = 0; k < 64; k++) s += o_s[wl][k] * Wef[k * 32 + lane];
    z_s[wl][lane] = s;
    out_z[(size_t)gw * 32 + lane] = s;
    __syncwarp();

    // ---- hd (64 wide)
    float c0 = bdf[lane], c1 = bdf[lane + 32];
#pragma unroll
    for (int k = 0; k < 32; k++) {
        float zk = z_s[wl][k];
        c0 += zk * Wdf[k * 64 + lane];
        c1 += zk * Wdf[k * 64 + lane + 32];
    }
    g_hd[(size_t)gw * 64 + lane]      = fmaxf(c0, 0.f);
    g_hd[(size_t)gw * 64 + lane + 32] = fmaxf(c1, 0.f);

    // ---- pred (3 wide)
    if (lane < 3) {
        float p = bc[lane];
#pragma unroll
        for (int k = 0; k < 32; k++) p += z_s[wl][k] * Wc[k * 3 + lane];
        out_pr[(size_t)gw * 3 + lane] = p;
    }
}

// ---------------------------- prop_hd: gather propagation of hd (dim 64)
__global__ void k_prop_hd(int n) {
    int gw = (blockIdx.x * blockDim.x + threadIdx.x) >> 5;
    int lane = threadIdx.x & 31;
    if (gw >= n) return;
    float di = g_dinv[gw];
    u64 dii = pack2(di * di, di * di);
    u64 self = ((const u64*)(g_hd + (size_t)gw * 64))[lane];
    u64 acc = 0ull;
    ffma2(acc, self, dii);
    int e = g_rowptr[gw], end = g_rowptr[gw + 1];
    for (; e + 2 <= end; e += 2) {
        int2 e0 = g_csr[e], e1 = g_csr[e + 1];
        u64 v0 = ((const u64*)(g_hd + (size_t)e0.x * 64))[lane];
        u64 v1 = ((const u64*)(g_hd + (size_t)e1.x * 64))[lane];
        ffma2(acc, v0, pack2(__int_as_float(e0.y), __int_as_float(e0.y)));
        ffma2(acc, v1, pack2(__int_as_float(e1.y), __int_as_float(e1.y)));
    }
    if (e < end) {
        int2 e0 = g_csr[e];
        u64 v0 = ((const u64*)(g_hd + (size_t)e0.x * 64))[lane];
        ffma2(acc, v0, pack2(__int_as_float(e0.y), __int_as_float(e0.y)));
    }
    ((u64*)(g_pd + (size_t)gw * 64))[lane] = acc;
}

// ------------------- GEMM2: x_recon = (A_norm hd) @ W_dec + b_dec
// warp-per-row, pd broadcast via shfl, W in 64KB smem, f32x2 FMAs
__global__ void k_gemm2(const float* __restrict__ W, const float* __restrict__ b,
                        float* __restrict__ outx, int n) {
    extern __shared__ float Wsm[];  // 64*256 floats
    for (int i = threadIdx.x; i < 64 * 256 / 4; i += blockDim.x)
        ((float4*)Wsm)[i] = ((const float4*)W)[i];
    __syncthreads();

    int gw = (blockIdx.x * blockDim.x + threadIdx.x) >> 5;
    int lane = threadIdx.x & 31;
    if (gw >= n) return;

    float2 hv = ((const float2*)(g_pd + (size_t)gw * 64))[lane];  // k = 2*lane, 2*lane+1
    u64 acc[4] = {0ull, 0ull, 0ull, 0ull};
    const ulonglong2* W2 = (const ulonglong2*)Wsm;  // 64 ulonglong2 per row
#pragma unroll
    for (int k = 0; k < 64; k++) {
        float hk = __shfl_sync(0xFFFFFFFFu, (k & 1) ? hv.y : hv.x, k >> 1);
        u64 hh = pack2(hk, hk);
        ulonglong2 w0 = W2[k * 64 + lane];
        ulonglong2 w1 = W2[k * 64 + 32 + lane];
        ffma2(acc[0], hh, w0.x);
        ffma2(acc[1], hh, w0.y);
        ffma2(acc[2], hh, w1.x);
        ffma2(acc[3], hh, w1.y);
    }
    const ulonglong2* b2 = (const ulonglong2*)b;
    ulonglong2 b0 = b2[lane], b1 = b2[lane + 32];
    ulonglong2 t0, t1;
    t0.x = add2(acc[0], b0.x); t0.y = add2(acc[1], b0.y);
    t1.x = add2(acc[2], b1.x); t1.y = add2(acc[3], b1.y);
    ulonglong2* o = (ulonglong2*)(outx + (size_t)gw * 256);
    o[lane] = t0;
    o[lane + 32] = t1;
}

// ---------------------------------------------------------------------------
extern "C" void kernel_launch(void* const* d_in, const int* in_sizes, int n_in,
                              void* d_out, int out_size) {
    const float* x     = (const float*)d_in[0];
    const int*   ei    = (const int*)d_in[1];
    // d_in[2] = edge_attr (unused by reference)
    const float* W_enc = (const float*)d_in[3];
    const float* b_enc = (const float*)d_in[4];
    const float* W_ef  = (const float*)d_in[5];
    const float* b_ef  = (const float*)d_in[6];
    const float* W_df  = (const float*)d_in[7];
    const float* b_df  = (const float*)d_in[8];
    const float* W_dec = (const float*)d_in[9];
    const float* b_dec = (const float*)d_in[10];
    const float* W_c   = (const float*)d_in[11];
    const float* b_c   = (const float*)d_in[12];

    int N = in_sizes[0] / 256;
    int E = in_sizes[1] / 2;
    const int* src = ei;
    const int* dst = ei + E;

    float* out    = (float*)d_out;
    float* out_xr = out;
    float* out_z  = out + (size_t)N * 256;
    float* out_pr = out_z + (size_t)N * 32;

    cudaFuncSetAttribute(k_gemm1, cudaFuncAttributeMaxDynamicSharedMemorySize, 65536);
    cudaFuncSetAttribute(k_gemm2, cudaFuncAttributeMaxDynamicSharedMemorySize, 65536);

    int gbN   = (N + 255) / 256;
    int gbE   = (E + 255) / 256;
    int gbW   = (N + 7) / 8;          // warp-per-node, 8 warps/block
    int nblk  = (N + 1023) / 1024;    // scan blocks

    k_init     <<<gbN, 256>>>(N);
    k_count    <<<gbE, 256>>>(dst, E);
    k_scan_a   <<<nblk, 1024>>>(N);
    k_scan_b   <<<1, 128>>>(nblk);
    k_scan_c   <<<gbN, 256>>>(N);
    k_fill     <<<gbE, 256>>>(src, dst, E);
    k_gemm1    <<<gbN, 256, 65536>>>(x, W_enc, N);
    k_prop1_mlp<<<gbW, 256>>>(b_enc, W_ef, b_ef, W_df, b_df, W_c, b_c, out_z, out_pr, N);
    k_prop_hd  <<<gbW, 256>>>(N);
    k_gemm2    <<<gbW, 256, 65536>>>(W_dec, b_dec, out_xr, N);
}

// round 5
// speedup vs baseline: 1.8172x; 1.3562x over previous
#include <cuda_runtime.h>

// ---------------------------------------------------------------------------
// GNN VAE on GB300. CSR-by-dst build (hierarchical scan), gather propagation
// (no float atomics). Decoder GCN: propagate-then-transform.
// GEMM2: 8 rows/warp so W smem reads amortize (was smem-port bound).
// ---------------------------------------------------------------------------

#define MAXN 50048
#define MAXE 800256

typedef unsigned long long u64;

__device__ __forceinline__ u64 pack2(float x, float y) {
    u64 r; asm("mov.b64 %0, {%1,%2};" : "=l"(r) : "f"(x), "f"(y)); return r;
}
__device__ __forceinline__ void ffma2(u64 &d, u64 a, u64 b) {
    asm("fma.rn.f32x2 %0, %1, %2, %0;" : "+l"(d) : "l"(a), "l"(b));
}
__device__ __forceinline__ u64 add2(u64 a, u64 b) {
    u64 r; asm("add.rn.f32x2 %0, %1, %2;" : "=l"(r) : "l"(a), "l"(b)); return r;
}

__device__ int   g_cnt[MAXN];
__device__ int   g_cursor[MAXN];
__device__ int   g_rowptr[MAXN + 1];
__device__ int   g_bsum[128];
__device__ int   g_boff[128];
__device__ float g_dinv[MAXN];
__device__ __align__(16) int2  g_csr[MAXE];               // {src, weight bits}
__device__ __align__(256) float g_h1[(size_t)MAXN * 64];  // x @ W_enc_gnn
__device__ __align__(256) float g_hd[(size_t)MAXN * 64];  // relu(z @ W_dec_fc + b)
__device__ __align__(256) float g_pd[(size_t)MAXN * 64];  // A_norm @ hd

// ---------------------------------------------------------------- init / deg
__global__ void k_init(int n) {
    int i = blockIdx.x * blockDim.x + threadIdx.x;
    if (i < n) g_cnt[i] = 0;
}

__global__ void k_count(const int* __restrict__ dst, int E) {
    int i = blockIdx.x * blockDim.x + threadIdx.x;
    if (i < E) atomicAdd(&g_cnt[dst[i]], 1);
}

// ----------------------------------------------------- hierarchical scan
__global__ void k_scan_a(int n) {
    __shared__ int wsum[32];
    int t = threadIdx.x;
    int gid = blockIdx.x * 1024 + t;
    int lane = t & 31, w = t >> 5;
    int v = (gid < n) ? g_cnt[gid] : 0;
    int s = v;
#pragma unroll
    for (int o = 1; o < 32; o <<= 1) {
        int u = __shfl_up_sync(0xFFFFFFFFu, s, o);
        if (lane >= o) s += u;
    }
    if (lane == 31) wsum[w] = s;
    __syncthreads();
    if (w == 0) {
        int ws = wsum[lane];
#pragma unroll
        for (int o = 1; o < 32; o <<= 1) {
            int u = __shfl_up_sync(0xFFFFFFFFu, ws, o);
            if (lane >= o) ws += u;
        }
        wsum[lane] = ws;
    }
    __syncthreads();
    int incl = s + (w > 0 ? wsum[w - 1] : 0);
    if (gid < n) g_rowptr[gid + 1] = incl;
    if (t == 1023) g_bsum[blockIdx.x] = incl;
}

__global__ void k_scan_b(int nblk) {
    __shared__ int sh[128];
    int t = threadIdx.x;
    sh[t] = (t < nblk) ? g_bsum[t] : 0;
    __syncthreads();
#pragma unroll
    for (int o = 1; o < 128; o <<= 1) {
        int u = (t >= o) ? sh[t - o] : 0;
        __syncthreads();
        sh[t] += u;
        __syncthreads();
    }
    g_boff[t] = (t > 0) ? sh[t - 1] : 0;
    if (t == 0) g_rowptr[0] = 0;
}

__global__ void k_scan_c(int n) {
    int i = blockIdx.x * blockDim.x + threadIdx.x;
    if (i >= n) return;
    g_rowptr[i + 1] += g_boff[i >> 10];
    g_dinv[i] = rsqrtf((float)(g_cnt[i] + 1));  // +1 self loop
    g_cursor[i] = 0;
}

__global__ void k_fill(const int* __restrict__ src, const int* __restrict__ dst, int E) {
    int i = blockIdx.x * blockDim.x + threadIdx.x;
    if (i >= E) return;
    int s = src[i], d = dst[i];
    int pos = atomicAdd(&g_cursor[d], 1);
    float w = g_dinv[s] * g_dinv[d];
    g_csr[g_rowptr[d] + pos] = make_int2(s, __float_as_int(w));
}

// ---------------------------------------------------- GEMM1: [N,256]@[256,64]
// thread-per-row; W smem reads are lane-invariant -> broadcast (free-ish)
__global__ void k_gemm1(const float* __restrict__ x, const float* __restrict__ W, int n) {
    extern __shared__ float Wsm[];  // 256*64 floats
    for (int i = threadIdx.x; i < 256 * 64 / 4; i += blockDim.x)
        ((float4*)Wsm)[i] = ((const float4*)W)[i];
    __syncthreads();

    int row = blockIdx.x * blockDim.x + threadIdx.x;
    if (row >= n) return;

    u64 acc[32];
#pragma unroll
    for (int j = 0; j < 32; j++) acc[j] = 0ull;

    const float4* xr = (const float4*)(x + (size_t)row * 256);
    for (int k4 = 0; k4 < 64; k4++) {
        float4 xv = __ldg(xr + k4);
#pragma unroll
        for (int kk = 0; kk < 4; kk++) {
            float xk = (kk == 0) ? xv.x : (kk == 1) ? xv.y : (kk == 2) ? xv.z : xv.w;
            u64 xx = pack2(xk, xk);
            const ulonglong2* wrow = (const ulonglong2*)(Wsm + (k4 * 4 + kk) * 64);
#pragma unroll
            for (int j = 0; j < 16; j++) {
                ulonglong2 w = wrow[j];
                ffma2(acc[2 * j],     xx, w.x);
                ffma2(acc[2 * j + 1], xx, w.y);
            }
        }
    }
    ulonglong2* o = (ulonglong2*)(g_h1 + (size_t)row * 64);
#pragma unroll
    for (int j = 0; j < 16; j++) { ulonglong2 t; t.x = acc[2 * j]; t.y = acc[2 * j + 1]; o[j] = t; }
}

// ------------- fused: prop1 (gather, 64-d, +bias +relu) THEN encoder MLPs
__global__ void k_prop1_mlp(const float* __restrict__ b,
                            const float* __restrict__ Wef, const float* __restrict__ bef,
                            const float* __restrict__ Wdf, const float* __restrict__ bdf,
                            const float* __restrict__ Wc,  const float* __restrict__ bc,
                            float* __restrict__ out_z, float* __restrict__ out_pr, int n) {
    __shared__ float o_s[8][64];
    __shared__ float z_s[8][32];
    int wl = threadIdx.x >> 5, lane = threadIdx.x & 31;
    int gw = (blockIdx.x * blockDim.x + threadIdx.x) >> 5;
    if (gw >= n) return;

    float di = g_dinv[gw];
    u64 dii = pack2(di * di, di * di);
    u64 self = ((const u64*)(g_h1 + (size_t)gw * 64))[lane];
    u64 acc = 0ull;
    ffma2(acc, self, dii);
    int e = g_rowptr[gw], end = g_rowptr[gw + 1];
    for (; e + 2 <= end; e += 2) {
        int2 e0 = g_csr[e], e1 = g_csr[e + 1];
        u64 v0 = ((const u64*)(g_h1 + (size_t)e0.x * 64))[lane];
        u64 v1 = ((const u64*)(g_h1 + (size_t)e1.x * 64))[lane];
        ffma2(acc, v0, pack2(__int_as_float(e0.y), __int_as_float(e0.y)));
        ffma2(acc, v1, pack2(__int_as_float(e1.y), __int_as_float(e1.y)));
    }
    if (e < end) {
        int2 e0 = g_csr[e];
        u64 v0 = ((const u64*)(g_h1 + (size_t)e0.x * 64))[lane];
        ffma2(acc, v0, pack2(__int_as_float(e0.y), __int_as_float(e0.y)));
    }
    float2 r = *(float2*)&acc;
    float2 bf = ((const float2*)b)[lane];
    r.x = fmaxf(r.x + bf.x, 0.f);
    r.y = fmaxf(r.y + bf.y, 0.f);
    o_s[wl][2 * lane]     = r.x;
    o_s[wl][2 * lane + 1] = r.y;
    __syncwarp();

    float s = bef[lane];
#pragma unroll
    for (int k = 0; k < 64; k++) s += o_s[wl][k] * Wef[k * 32 + lane];
    z_s[wl][lane] = s;
    out_z[(size_t)gw * 32 + lane] = s;
    __syncwarp();

    float c0 = bdf[lane], c1 = bdf[lane + 32];
#pragma unroll
    for (int k = 0; k < 32; k++) {
        float zk = z_s[wl][k];
        c0 += zk * Wdf[k * 64 + lane];
        c1 += zk * Wdf[k * 64 + lane + 32];
    }
    g_hd[(size_t)gw * 64 + lane]      = fmaxf(c0, 0.f);
    g_hd[(size_t)gw * 64 + lane + 32] = fmaxf(c1, 0.f);

    if (lane < 3) {
        float p = bc[lane];
#pragma unroll
        for (int k = 0; k < 32; k++) p += z_s[wl][k] * Wc[k * 3 + lane];
        out_pr[(size_t)gw * 3 + lane] = p;
    }
}

// ---------------------------- prop_hd: gather propagation of hd (dim 64)
__global__ void k_prop_hd(int n) {
    int gw = (blockIdx.x * blockDim.x + threadIdx.x) >> 5;
    int lane = threadIdx.x & 31;
    if (gw >= n) return;
    float di = g_dinv[gw];
    u64 dii = pack2(di * di, di * di);
    u64 self = ((const u64*)(g_hd + (size_t)gw * 64))[lane];
    u64 acc = 0ull;
    ffma2(acc, self, dii);
    int e = g_rowptr[gw], end = g_rowptr[gw + 1];
    for (; e + 2 <= end; e += 2) {
        int2 e0 = g_csr[e], e1 = g_csr[e + 1];
        u64 v0 = ((const u64*)(g_hd + (size_t)e0.x * 64))[lane];
        u64 v1 = ((const u64*)(g_hd + (size_t)e1.x * 64))[lane];
        ffma2(acc, v0, pack2(__int_as_float(e0.y), __int_as_float(e0.y)));
        ffma2(acc, v1, pack2(__int_as_float(e1.y), __int_as_float(e1.y)));
    }
    if (e < end) {
        int2 e0 = g_csr[e];
        u64 v0 = ((const u64*)(g_hd + (size_t)e0.x * 64))[lane];
        ffma2(acc, v0, pack2(__int_as_float(e0.y), __int_as_float(e0.y)));
    }
    ((u64*)(g_pd + (size_t)gw * 64))[lane] = acc;
}

// ------------------- GEMM2: x_recon = (A_norm hd) @ W_dec + b_dec
// 8 rows per warp: W smem reads amortized 8x; pd broadcast via shfl.
#define G2R 8
__global__ void k_gemm2(const float* __restrict__ W, const float* __restrict__ b,
                        float* __restrict__ outx, int n) {
    extern __shared__ float Wsm[];  // 64*256 floats
    for (int i = threadIdx.x; i < 64 * 256 / 4; i += blockDim.x)
        ((float4*)Wsm)[i] = ((const float4*)W)[i];
    __syncthreads();

    int gw = (blockIdx.x * blockDim.x + threadIdx.x) >> 5;
    int lane = threadIdx.x & 31;
    int r0 = gw * G2R;
    if (r0 >= n) return;

    // preload pd for 8 rows: hv[j] = pd[(r0+j)*64 + 2*lane .. +1] (coalesced)
    float2 hv[G2R];
#pragma unroll
    for (int j = 0; j < G2R; j++)
        hv[j] = ((const float2*)(g_pd + (size_t)(r0 + j) * 64))[lane];

    // lane owns cols [4*lane,4*lane+4) and [128+4*lane, ...): 2 ulonglong2 per row
    u64 acc[G2R][4];
#pragma unroll
    for (int j = 0; j < G2R; j++)
#pragma unroll
        for (int c = 0; c < 4; c++) acc[j][c] = 0ull;

    const ulonglong2* W2 = (const ulonglong2*)Wsm;  // 64 ulonglong2 per k-row
#pragma unroll
    for (int k = 0; k < 64; k++) {
        ulonglong2 w0 = W2[k * 64 + lane];
        ulonglong2 w1 = W2[k * 64 + 32 + lane];
#pragma unroll
        for (int j = 0; j < G2R; j++) {
            float hk = __shfl_sync(0xFFFFFFFFu, (k & 1) ? hv[j].y : hv[j].x, k >> 1);
            u64 hh = pack2(hk, hk);
            ffma2(acc[j][0], hh, w0.x);
            ffma2(acc[j][1], hh, w0.y);
            ffma2(acc[j][2], hh, w1.x);
            ffma2(acc[j][3], hh, w1.y);
        }
    }
    const ulonglong2* b2 = (const ulonglong2*)b;
    ulonglong2 b0 = b2[lane], b1 = b2[lane + 32];
#pragma unroll
    for (int j = 0; j < G2R; j++) {
        int row = r0 + j;
        if (row >= n) break;
        ulonglong2 t0, t1;
        t0.x = add2(acc[j][0], b0.x); t0.y = add2(acc[j][1], b0.y);
        t1.x = add2(acc[j][2], b1.x); t1.y = add2(acc[j][3], b1.y);
        ulonglong2* o = (ulonglong2*)(outx + (size_t)row * 256);
        o[lane] = t0;
        o[lane + 32] = t1;
    }
}

// ---------------------------------------------------------------------------
extern "C" void kernel_launch(void* const* d_in, const int* in_sizes, int n_in,
                              void* d_out, int out_size) {
    const float* x     = (const float*)d_in[0];
    const int*   ei    = (const int*)d_in[1];
    // d_in[2] = edge_attr (unused by reference)
    const float* W_enc = (const float*)d_in[3];
    const float* b_enc = (const float*)d_in[4];
    const float* W_ef  = (const float*)d_in[5];
    const float* b_ef  = (const float*)d_in[6];
    const float* W_df  = (const float*)d_in[7];
    const float* b_df  = (const float*)d_in[8];
    const float* W_dec = (const float*)d_in[9];
    const float* b_dec = (const float*)d_in[10];
    const float* W_c   = (const float*)d_in[11];
    const float* b_c   = (const float*)d_in[12];

    int N = in_sizes[0] / 256;
    int E = in_sizes[1] / 2;
    const int* src = ei;
    const int* dst = ei + E;

    float* out    = (float*)d_out;
    float* out_xr = out;
    float* out_z  = out + (size_t)N * 256;
    float* out_pr = out_z + (size_t)N * 32;

    cudaFuncSetAttribute(k_gemm1, cudaFuncAttributeMaxDynamicSharedMemorySize, 65536);
    cudaFuncSetAttribute(k_gemm2, cudaFuncAttributeMaxDynamicSharedMemorySize, 65536);

    int gbN   = (N + 255) / 256;
    int gbE   = (E + 255) / 256;
    int gbW   = (N + 7) / 8;                    // warp-per-node, 8 warps/block
    int nwarp2 = (N + G2R - 1) / G2R;           // gemm2: 8 rows per warp
    int gbG2  = (nwarp2 * 32 + 255) / 256;
    int nblk  = (N + 1023) / 1024;

    k_init     <<<gbN, 256>>>(N);
    k_count    <<<gbE, 256>>>(dst, E);
    k_scan_a   <<<nblk, 1024>>>(N);
    k_scan_b   <<<1, 128>>>(nblk);
    k_scan_c   <<<gbN, 256>>>(N);
    k_fill     <<<gbE, 256>>>(src, dst, E);
    k_gemm1    <<<gbN, 256, 65536>>>(x, W_enc, N);
    k_prop1_mlp<<<gbW, 256>>>(b_enc, W_ef, b_ef, W_df, b_df, W_c, b_c, out_z, out_pr, N);
    k_prop_hd  <<<gbW, 256>>>(N);
    k_gemm2    <<<gbG2, 256, 65536>>>(W_dec, b_dec, out_xr, N);
}